// round 1
// baseline (speedup 1.0000x reference)
#include <cuda_runtime.h>
#include <math.h>

#define B_   16
#define C_   32
#define H_   256
#define W_   256
#define K_   256
#define PX   64
#define NPIX (B_*H_*W_)

typedef unsigned long long u64;
typedef unsigned int u32;

// ---------------- scratch (static device globals; no allocations) -------------
__device__ __align__(16) float g_state[(size_t)NPIX*C_];   // channels-last (b,y,x,c)
__device__ __align__(16) float g_h[(size_t)NPIX*C_];       // relu(conv3x3) at step 0
__device__ __align__(16) unsigned char g_idx[2][NPIX];     // ping-pong code indices
__device__ __align__(16) float g_up1_tab[9*K_*C_];         // [offset][code][ch]
__device__ __align__(16) float g_tau_tab[K_*C_];           // tau conv of each code (+bias)
__device__ __align__(16) float g_dec_tab[K_];              // sigmoid(dec of each code)
__device__ __align__(16) float g_cnh[K_];                  // 0.5*||code||^2
__device__ __align__(16) float g_cbT[C_*K_];               // codebook transposed [c][k]

// ---------------- f32x2 helpers (Blackwell packed fp32) -----------------------
__device__ __forceinline__ u64 f2_pack(float lo, float hi){
    u64 r; u32 a=__float_as_uint(lo), b=__float_as_uint(hi);
    asm("mov.b64 %0,{%1,%2};":"=l"(r):"r"(a),"r"(b)); return r;
}
__device__ __forceinline__ u64 f2_splat(float v){
    u64 r; u32 a=__float_as_uint(v);
    asm("mov.b64 %0,{%1,%1};":"=l"(r):"r"(a)); return r;
}
__device__ __forceinline__ void f2_unpack(u64 p, float& lo, float& hi){
    u32 a,b; asm("mov.b64 {%0,%1},%2;":"=r"(a),"=r"(b):"l"(p));
    lo=__uint_as_float(a); hi=__uint_as_float(b);
}
__device__ __forceinline__ u64 f2_fma(u64 a,u64 b,u64 c){
    u64 d; asm("fma.rn.f32x2 %0,%1,%2,%3;":"=l"(d):"l"(a),"l"(b),"l"(c)); return d;
}
__device__ __forceinline__ u64 f2_add(u64 a,u64 b){
    u64 d; asm("add.rn.f32x2 %0,%1,%2;":"=l"(d):"l"(a),"l"(b)); return d;
}
__device__ __forceinline__ float sigm(float x){ return 1.f/(1.f+expf(-x)); }
__device__ __forceinline__ u32 ford(float f){
    u32 u=__float_as_uint(f);
    return (u & 0x80000000u) ? ~u : (u ^ 0x80000000u);
}

// ---------------- precompute tables -------------------------------------------
__global__ __launch_bounds__(256) void k_pre(
    const float* __restrict__ up1_w, const float* __restrict__ tau_w,
    const float* __restrict__ tau_b, const float* __restrict__ cb,
    const float* __restrict__ dec_w, const float* __restrict__ dec_b)
{
    int t = blockIdx.x*256 + threadIdx.x;
    if (t < 9*K_*C_){
        int c = t & 31; int k = (t>>5)&255; int o = t>>13;
        float s=0.f;
        #pragma unroll
        for (int i=0;i<32;i++) s += up1_w[c*288 + i*9 + o]*cb[k*32+i];
        g_up1_tab[t] = s;
        return;
    }
    int u = t - 9*K_*C_;
    if (u < K_*C_){
        int c=u&31, k=u>>5;
        float s=tau_b[c];
        #pragma unroll
        for (int i=0;i<32;i++) s += tau_w[c*32+i]*cb[k*32+i];
        g_tau_tab[u]=s; return;
    }
    u -= K_*C_;
    if (u < K_){
        float s=dec_b[0];
        #pragma unroll
        for(int i=0;i<32;i++) s+=dec_w[i]*cb[u*32+i];
        g_dec_tab[u]=sigm(s); return;
    }
    u -= K_;
    if (u < K_){
        float s=0.f;
        #pragma unroll
        for(int i=0;i<32;i++){float v=cb[u*32+i]; s+=v*v;}
        g_cnh[u]=0.5f*s; return;
    }
    u -= K_;
    if (u < C_*K_){
        int c=u>>8, k=u&255;
        g_cbT[u]=cb[k*32+c];
    }
}

// ---------------- stem: relu(conv3x3 1->32) -> g_state (channels-last) --------
__global__ __launch_bounds__(256) void k_stem(
    const float* __restrict__ x, const float* __restrict__ sw,
    const float* __restrict__ sb)
{
    __shared__ float sx[3*66];
    __shared__ float s_w[9*32];
    __shared__ float s_b[32];
    int tid=threadIdx.x;
    int x0 = blockIdx.x*PX, y = blockIdx.y, b = blockIdx.z;
    for (int e=tid;e<198;e+=256){
        int r=e/66, col=e%66;
        int gy=y+r-1, gx=x0+col-1;
        sx[e] = (gy>=0 && gy<H_ && gx>=0 && gx<W_) ? x[(b*H_+gy)*W_+gx] : 0.f;
    }
    for (int e=tid;e<288;e+=256){ int o=e>>5, c=e&31; s_w[e]=sw[c*9+o]; }
    if (tid<32) s_b[tid]=sb[tid];
    __syncthreads();
    int px=tid>>2, c0=(tid&3)<<3;
    float acc[8];
    #pragma unroll
    for(int i=0;i<8;i++) acc[i]=s_b[c0+i];
    #pragma unroll
    for (int o=0;o<9;o++){
        float v = sx[(o/3)*66 + px + (o%3)];
        #pragma unroll
        for(int i=0;i<8;i++) acc[i] = fmaf(v, s_w[o*32+c0+i], acc[i]);
    }
    int pix = (b*H_+y)*W_ + x0 + px;
    float* out = &g_state[(size_t)pix*32 + c0];
    #pragma unroll
    for(int i=0;i<8;i++) out[i] = fmaxf(acc[i],0.f);
}

// ---------------- step-0 heavy conv: g_h = relu(conv3x3(g_state, up1)) --------
__global__ __launch_bounds__(256) void k_conv1(
    const float* __restrict__ up1_w, const float* __restrict__ up1_b)
{
    extern __shared__ float sm[];
    float* st  = sm;             // 3*66*33 (padded to 6560)
    float* s_w = sm + 6560;      // 9216, layout [o][i][c]
    float* s_b = s_w + 9216;     // 32
    int tid=threadIdx.x;
    int x0=blockIdx.x*PX, y=blockIdx.y, b=blockIdx.z;
    for (int e=tid;e<6336;e+=256){
        int i=e&31; int col=(e>>5)%66; int r=e/2112;
        int gy=y+r-1, gx=x0+col-1;
        float v=0.f;
        if (gy>=0 && gy<H_ && gx>=0 && gx<W_)
            v = g_state[(size_t)((b*H_+gy)*W_+gx)*32 + i];
        st[(r*66+col)*33 + i] = v;
    }
    for (int e=tid;e<9216;e+=256){
        int c=e&31; int i=(e>>5)&31; int o=e>>10;
        s_w[e] = up1_w[c*288 + i*9 + o];
    }
    if (tid<32) s_b[tid]=up1_b[tid];
    __syncthreads();
    int px = tid&63, c0=(tid>>6)<<3;
    u64 acc[4];
    acc[0]=f2_pack(s_b[c0+0],s_b[c0+1]);
    acc[1]=f2_pack(s_b[c0+2],s_b[c0+3]);
    acc[2]=f2_pack(s_b[c0+4],s_b[c0+5]);
    acc[3]=f2_pack(s_b[c0+6],s_b[c0+7]);
    #pragma unroll
    for (int o=0;o<9;o++){
        const float* stc = &st[((o/3)*66 + px + (o%3))*33];
        const float* wb  = &s_w[o*1024 + c0];
        #pragma unroll 8
        for (int i=0;i<32;i++){
            u64 v = f2_splat(stc[i]);
            ulonglong2 w01 = *(const ulonglong2*)(wb + i*32);
            ulonglong2 w23 = *(const ulonglong2*)(wb + i*32 + 4);
            acc[0]=f2_fma(w01.x,v,acc[0]); acc[1]=f2_fma(w01.y,v,acc[1]);
            acc[2]=f2_fma(w23.x,v,acc[2]); acc[3]=f2_fma(w23.y,v,acc[3]);
        }
    }
    int pix = (b*H_+y)*W_ + x0 + px;
    float r[8];
    f2_unpack(acc[0],r[0],r[1]); f2_unpack(acc[1],r[2],r[3]);
    f2_unpack(acc[2],r[4],r[5]); f2_unpack(acc[3],r[6],r[7]);
    float4* o4 = (float4*)&g_h[(size_t)pix*32 + c0];
    o4[0] = make_float4(fmaxf(r[0],0.f),fmaxf(r[1],0.f),fmaxf(r[2],0.f),fmaxf(r[3],0.f));
    o4[1] = make_float4(fmaxf(r[4],0.f),fmaxf(r[5],0.f),fmaxf(r[6],0.f),fmaxf(r[7],0.f));
}

// ---------------- shared VQ phase-2: scores GEMM (f32x2) + warp argmin --------
__device__ __forceinline__ void vq_phase2(
    const float* __restrict__ s_t,   // [32][64] z' transposed
    const float* __restrict__ cb_t,  // [32][256]
    const float* __restrict__ s_cn,  // [256] 0.5||c||^2
    int pix0, unsigned char* __restrict__ dst)
{
    int lane=threadIdx.x&31, w=threadIdx.x>>5;
    int p0=w*8, c0=lane*8;
    u64 acc[8][4];
    #pragma unroll
    for(int i=0;i<8;i++){ acc[i][0]=0; acc[i][1]=0; acc[i][2]=0; acc[i][3]=0; }
    #pragma unroll 4
    for (int k=0;k<32;k++){
        ulonglong2 z01=*(const ulonglong2*)&s_t[k*64+p0];
        ulonglong2 z23=*(const ulonglong2*)&s_t[k*64+p0+4];
        u64 z0=z01.x, z1=z01.y, z2=z23.x, z3=z23.y;
        float4 cva=*(const float4*)&cb_t[k*256+c0];
        float4 cvb=*(const float4*)&cb_t[k*256+c0+4];
        float cv[8]={cva.x,cva.y,cva.z,cva.w,cvb.x,cvb.y,cvb.z,cvb.w};
        #pragma unroll
        for(int i=0;i<8;i++){
            u64 ci=f2_splat(cv[i]);
            acc[i][0]=f2_fma(z0,ci,acc[i][0]);
            acc[i][1]=f2_fma(z1,ci,acc[i][1]);
            acc[i][2]=f2_fma(z2,ci,acc[i][2]);
            acc[i][3]=f2_fma(z3,ci,acc[i][3]);
        }
    }
    u64 best[8];
    #pragma unroll
    for(int j=0;j<4;j++){
        u64 klo=~0ull, khi=~0ull;
        #pragma unroll
        for(int i=0;i<8;i++){
            float lo,hi; f2_unpack(acc[i][j],lo,hi);
            float cn=s_cn[c0+i];
            u64 keyl=(((u64)ford(cn-lo))<<8)|(u32)(c0+i);
            u64 keyh=(((u64)ford(cn-hi))<<8)|(u32)(c0+i);
            klo = keyl<klo?keyl:klo; khi = keyh<khi?keyh:khi;
        }
        best[2*j]=klo; best[2*j+1]=khi;
    }
    #pragma unroll
    for(int pp=0;pp<8;pp++){
        u64 kk=best[pp];
        #pragma unroll
        for(int off=16;off>0;off>>=1){
            u64 o=__shfl_xor_sync(0xffffffffu,kk,off);
            kk = (o<kk)?o:kk;
        }
        if (lane==0) dst[pix0+p0+pp]=(unsigned char)(kk&0xffu);
    }
}

// ---------------- step 0 mix + VQ (continuous state) --------------------------
__global__ __launch_bounds__(256) void k_mixvq0(
    const float* __restrict__ up2_w, const float* __restrict__ up2_b,
    const float* __restrict__ tau_w, const float* __restrict__ tau_b)
{
    extern __shared__ float sm[];
    float* cb_t = sm;            // 8192
    float* sh   = cb_t+8192;     // 64*33
    float* sst  = sh+2112;       // 64*33
    float* s_t  = sst+2112;      // 32*64
    float* s_u2 = s_t+2048;      // 1024 [j][c]
    float* s_ta = s_u2+1024;     // 1024 [j][c]
    float* s_cn = s_ta+1024;     // 256
    float* s_u2b= s_cn+256;      // 32
    float* s_tab= s_u2b+32;      // 32
    int tid=threadIdx.x;
    int x0=blockIdx.x*PX, y=blockIdx.y, b=blockIdx.z;
    int pix0 = (b*H_+y)*W_ + x0;
    for (int e=tid;e<8192;e+=256) cb_t[e]=g_cbT[e];
    for (int e=tid;e<2048;e+=256){
        sh [(e>>5)*33+(e&31)] = g_h    [(size_t)pix0*32+e];
        sst[(e>>5)*33+(e&31)] = g_state[(size_t)pix0*32+e];
    }
    for (int e=tid;e<1024;e+=256){
        int j=e>>5,c=e&31;
        s_u2[e]=up2_w[c*32+j];
        s_ta[e]=tau_w[c*32+j];
    }
    s_cn[tid]=g_cnh[tid];
    if (tid<32){ s_u2b[tid]=up2_b[tid]; s_tab[tid]=tau_b[tid]; }
    __syncthreads();
    {
        int px=tid>>2, c0=(tid&3)<<3;
        u64 d[4]={f2_pack(s_u2b[c0],s_u2b[c0+1]),f2_pack(s_u2b[c0+2],s_u2b[c0+3]),
                  f2_pack(s_u2b[c0+4],s_u2b[c0+5]),f2_pack(s_u2b[c0+6],s_u2b[c0+7])};
        u64 t[4]={f2_pack(s_tab[c0],s_tab[c0+1]),f2_pack(s_tab[c0+2],s_tab[c0+3]),
                  f2_pack(s_tab[c0+4],s_tab[c0+5]),f2_pack(s_tab[c0+6],s_tab[c0+7])};
        #pragma unroll 8
        for (int j=0;j<32;j++){
            u64 hv=f2_splat(sh [px*33+j]);
            u64 sv=f2_splat(sst[px*33+j]);
            ulonglong2 w01=*(const ulonglong2*)&s_u2[j*32+c0];
            ulonglong2 w23=*(const ulonglong2*)&s_u2[j*32+c0+4];
            ulonglong2 q01=*(const ulonglong2*)&s_ta[j*32+c0];
            ulonglong2 q23=*(const ulonglong2*)&s_ta[j*32+c0+4];
            d[0]=f2_fma(w01.x,hv,d[0]); d[1]=f2_fma(w01.y,hv,d[1]);
            d[2]=f2_fma(w23.x,hv,d[2]); d[3]=f2_fma(w23.y,hv,d[3]);
            t[0]=f2_fma(q01.x,sv,t[0]); t[1]=f2_fma(q01.y,sv,t[1]);
            t[2]=f2_fma(q23.x,sv,t[2]); t[3]=f2_fma(q23.y,sv,t[3]);
        }
        #pragma unroll
        for (int jj=0;jj<4;jj++){
            float dl,dh,tl,th; f2_unpack(d[jj],dl,dh); f2_unpack(t[jj],tl,th);
            float sl=sst[px*33+c0+2*jj], shh=sst[px*33+c0+2*jj+1];
            float bl=sigm(tl), bh=sigm(th);
            s_t[(c0+2*jj  )*64+px]=dl+bl*(sl -dl);
            s_t[(c0+2*jj+1)*64+px]=dh+bh*(shh-dh);
        }
    }
    __syncthreads();
    vq_phase2(s_t, cb_t, s_cn, pix0, g_idx[0]);
}

// ---------------- steps 1..4 : fully table-driven, idx -> idx -----------------
__global__ __launch_bounds__(256) void k_step(
    const float* __restrict__ up2_w, const float* __restrict__ up2_b,
    const float* __restrict__ up1_b, int src)
{
    extern __shared__ float sm[];
    float* cb_t = sm;            // 8192  [c][k]
    float* sh   = cb_t+8192;     // 64*33
    float* s_t  = sh+2112;       // 32*64
    float* s_u2 = s_t+2048;      // 1024 [j][c]
    float* s_cn = s_u2+1024;     // 256
    float* s_u2b= s_cn+256;      // 32
    int*   s_id = (int*)(s_u2b+32); // 3*66
    const unsigned char* __restrict__ gin = g_idx[src];
    unsigned char* __restrict__ gout = g_idx[src^1];
    int tid=threadIdx.x;
    int x0=blockIdx.x*PX, y=blockIdx.y, b=blockIdx.z;
    int pix0 = (b*H_+y)*W_ + x0;
    for (int e=tid;e<8192;e+=256) cb_t[e]=g_cbT[e];
    for (int e=tid;e<1024;e+=256){ int j=e>>5,c=e&31; s_u2[e]=up2_w[c*32+j]; }
    s_cn[tid]=g_cnh[tid];
    if (tid<32) s_u2b[tid]=up2_b[tid];
    for (int e=tid;e<198;e+=256){
        int r=e/66, col=e%66;
        int gy=y+r-1, gx=x0+col-1;
        s_id[e] = (gy>=0 && gy<H_ && gx>=0 && gx<W_) ? (int)gin[(b*H_+gy)*W_+gx] : -1;
    }
    __syncthreads();
    int px=tid>>2, c0=(tid&3)<<3;
    // phase 1a: h = relu(up1_b + sum over 9 offsets of table rows)
    {
        float4 b0=*(const float4*)&up1_b[c0];
        float4 b1=*(const float4*)&up1_b[c0+4];
        u64 a[4]={f2_pack(b0.x,b0.y),f2_pack(b0.z,b0.w),
                  f2_pack(b1.x,b1.y),f2_pack(b1.z,b1.w)};
        #pragma unroll
        for(int o=0;o<9;o++){
            int kk=s_id[(o/3)*66+px+(o%3)];
            if (kk>=0){
                const ulonglong2* tp=(const ulonglong2*)&g_up1_tab[((o<<8)+kk)*32+c0];
                ulonglong2 v0=tp[0], v1=tp[1];
                a[0]=f2_add(a[0],v0.x); a[1]=f2_add(a[1],v0.y);
                a[2]=f2_add(a[2],v1.x); a[3]=f2_add(a[3],v1.y);
            }
        }
        #pragma unroll
        for(int j=0;j<4;j++){
            float lo,hi; f2_unpack(a[j],lo,hi);
            sh[px*33+c0+2*j  ]=fmaxf(lo,0.f);
            sh[px*33+c0+2*j+1]=fmaxf(hi,0.f);
        }
    }
    __syncthreads();
    // phase 1b: delta = up2@h + b ; beta = sigmoid(tau_tab[k]) ; z' = mix
    {
        int kself = s_id[66 + px + 1];
        u64 d[4]={f2_pack(s_u2b[c0],s_u2b[c0+1]),f2_pack(s_u2b[c0+2],s_u2b[c0+3]),
                  f2_pack(s_u2b[c0+4],s_u2b[c0+5]),f2_pack(s_u2b[c0+6],s_u2b[c0+7])};
        #pragma unroll 8
        for (int j=0;j<32;j++){
            u64 hv=f2_splat(sh[px*33+j]);
            ulonglong2 w01=*(const ulonglong2*)&s_u2[j*32+c0];
            ulonglong2 w23=*(const ulonglong2*)&s_u2[j*32+c0+4];
            d[0]=f2_fma(w01.x,hv,d[0]); d[1]=f2_fma(w01.y,hv,d[1]);
            d[2]=f2_fma(w23.x,hv,d[2]); d[3]=f2_fma(w23.y,hv,d[3]);
        }
        float4 t0=*(const float4*)&g_tau_tab[kself*32+c0];
        float4 t1=*(const float4*)&g_tau_tab[kself*32+c0+4];
        float tp[8]={t0.x,t0.y,t0.z,t0.w,t1.x,t1.y,t1.z,t1.w};
        #pragma unroll
        for (int jj=0;jj<4;jj++){
            float dl,dh; f2_unpack(d[jj],dl,dh);
            float sl =cb_t[(c0+2*jj  )*256+kself];
            float shh=cb_t[(c0+2*jj+1)*256+kself];
            float bl=sigm(tp[2*jj]), bh=sigm(tp[2*jj+1]);
            s_t[(c0+2*jj  )*64+px]=dl+bl*(sl -dl);
            s_t[(c0+2*jj+1)*64+px]=dh+bh*(shh-dh);
        }
    }
    __syncthreads();
    vq_phase2(s_t, cb_t, s_cn, pix0, gout);
}

// ---------------- decode: pure LUT ---------------------------------------------
__global__ __launch_bounds__(256) void k_dec(float* __restrict__ out, int fin)
{
    __shared__ float tab[256];
    tab[threadIdx.x]=g_dec_tab[threadIdx.x];
    __syncthreads();
    int t=blockIdx.x*256+threadIdx.x;
    uchar4 iv=*(const uchar4*)&g_idx[fin][t*4];
    ((float4*)out)[t]=make_float4(tab[iv.x],tab[iv.y],tab[iv.z],tab[iv.w]);
}

// ---------------- launch --------------------------------------------------------
extern "C" void kernel_launch(void* const* d_in, const int* in_sizes, int n_in,
                              void* d_out, int out_size)
{
    const float* x      =(const float*)d_in[0];
    const float* stem_w =(const float*)d_in[1];
    const float* stem_b =(const float*)d_in[2];
    const float* up1_w  =(const float*)d_in[3];
    const float* up1_b  =(const float*)d_in[4];
    const float* up2_w  =(const float*)d_in[5];
    const float* up2_b  =(const float*)d_in[6];
    const float* tau_w  =(const float*)d_in[7];
    const float* tau_b  =(const float*)d_in[8];
    const float* cb     =(const float*)d_in[9];
    const float* dec_w  =(const float*)d_in[10];
    const float* dec_b  =(const float*)d_in[11];
    (void)in_sizes; (void)n_in; (void)out_size;

    const size_t sm_conv1=(size_t)(6560+9216+32)*4;
    const size_t sm_mix  =(size_t)(8192+2112+2112+2048+1024+1024+256+32+32)*4;
    const size_t sm_step =(size_t)(8192+2112+2048+1024+256+32)*4 + 198*4;
    cudaFuncSetAttribute(k_conv1,  cudaFuncAttributeMaxDynamicSharedMemorySize,(int)sm_conv1);
    cudaFuncSetAttribute(k_mixvq0, cudaFuncAttributeMaxDynamicSharedMemorySize,(int)sm_mix);
    cudaFuncSetAttribute(k_step,   cudaFuncAttributeMaxDynamicSharedMemorySize,(int)sm_step);

    dim3 grid(W_/PX, H_, B_);
    k_pre   <<<354, 256>>>(up1_w, tau_w, tau_b, cb, dec_w, dec_b);
    k_stem  <<<grid,256>>>(x, stem_w, stem_b);
    k_conv1 <<<grid,256,sm_conv1>>>(up1_w, up1_b);
    k_mixvq0<<<grid,256,sm_mix  >>>(up2_w, up2_b, tau_w, tau_b);
    for (int t=1;t<5;t++)
        k_step<<<grid,256,sm_step>>>(up2_w, up2_b, up1_b, (t-1)&1);
    k_dec   <<<1024,256>>>((float*)d_out, 0);
}

// round 2
// speedup vs baseline: 1.3758x; 1.3758x over previous
#include <cuda_runtime.h>
#include <math.h>

#define B_   16
#define C_   32
#define H_   256
#define W_   256
#define K_   256
#define PX   64
#define NPIX (B_*H_*W_)

typedef unsigned long long u64;
typedef unsigned int u32;

// ---------------- scratch (static device globals; no allocations) -------------
__device__ __align__(16) float g_state[(size_t)NPIX*C_];   // channels-last (b,y,x,c)
__device__ __align__(16) float g_h[(size_t)NPIX*C_];       // relu(conv3x3) at step 0
__device__ __align__(16) unsigned char g_idx[2][NPIX];     // ping-pong code indices
__device__ __align__(16) float g_up1_tab[9*K_*C_];         // [offset][code][ch]
__device__ __align__(16) float g_tau_tab[K_*C_];           // tau conv of each code (+bias)
__device__ __align__(16) float g_dec_tab[K_];              // sigmoid(dec of each code)
__device__ __align__(16) float g_cnh[K_];                  // 0.5*||code||^2
__device__ __align__(16) float g_cbT[C_*K_];               // codebook [channel][code]
__device__ __align__(16) float g_w1t[9*C_*C_];             // up1 weights [o][i][c]
__device__ __align__(16) float g_u2t[C_*C_];               // up2 weights [j][c]
__device__ __align__(16) float g_taT[C_*C_];               // tau weights [j][c]

// ---------------- f32x2 helpers (Blackwell packed fp32) -----------------------
__device__ __forceinline__ u64 f2_pack(float lo, float hi){
    u64 r; u32 a=__float_as_uint(lo), b=__float_as_uint(hi);
    asm("mov.b64 %0,{%1,%2};":"=l"(r):"r"(a),"r"(b)); return r;
}
__device__ __forceinline__ u64 f2_splat(float v){
    u64 r; u32 a=__float_as_uint(v);
    asm("mov.b64 %0,{%1,%1};":"=l"(r):"r"(a)); return r;
}
__device__ __forceinline__ void f2_unpack(u64 p, float& lo, float& hi){
    u32 a,b; asm("mov.b64 {%0,%1},%2;":"=r"(a),"=r"(b):"l"(p));
    lo=__uint_as_float(a); hi=__uint_as_float(b);
}
__device__ __forceinline__ u64 f2_fma(u64 a,u64 b,u64 c){
    u64 d; asm("fma.rn.f32x2 %0,%1,%2,%3;":"=l"(d):"l"(a),"l"(b),"l"(c)); return d;
}
__device__ __forceinline__ u64 f2_add(u64 a,u64 b){
    u64 d; asm("add.rn.f32x2 %0,%1,%2;":"=l"(d):"l"(a),"l"(b)); return d;
}
__device__ __forceinline__ float sigm(float x){ return 1.f/(1.f+expf(-x)); }
__device__ __forceinline__ u32 ford(float f){
    u32 u=__float_as_uint(f);
    return (u & 0x80000000u) ? ~u : (u ^ 0x80000000u);
}

// ---------------- precompute tables -------------------------------------------
__global__ __launch_bounds__(256) void k_pre(
    const float* __restrict__ up1_w, const float* __restrict__ tau_w,
    const float* __restrict__ tau_b, const float* __restrict__ cb,
    const float* __restrict__ dec_w, const float* __restrict__ dec_b,
    const float* __restrict__ up2_w)
{
    int t = blockIdx.x*256 + threadIdx.x;
    if (t < 9*K_*C_){
        int c = t & 31; int k = (t>>5)&255; int o = t>>13;
        float s=0.f;
        #pragma unroll
        for (int i=0;i<32;i++) s += up1_w[c*288 + i*9 + o]*cb[k*32+i];
        g_up1_tab[t] = s;
        return;
    }
    int u = t - 9*K_*C_;
    if (u < K_*C_){
        int c=u&31, k=u>>5;
        float s=tau_b[c];
        #pragma unroll
        for (int i=0;i<32;i++) s += tau_w[c*32+i]*cb[k*32+i];
        g_tau_tab[u]=s; return;
    }
    u -= K_*C_;
    if (u < K_){
        float s=dec_b[0];
        #pragma unroll
        for(int i=0;i<32;i++) s+=dec_w[i]*cb[u*32+i];
        g_dec_tab[u]=sigm(s); return;
    }
    u -= K_;
    if (u < K_){
        float s=0.f;
        #pragma unroll
        for(int i=0;i<32;i++){float v=cb[u*32+i]; s+=v*v;}
        g_cnh[u]=0.5f*s; return;
    }
    u -= K_;
    if (u < C_*K_){
        int c=u>>8, k=u&255;
        g_cbT[u]=cb[k*32+c]; return;
    }
    u -= C_*K_;
    if (u < 9*C_*C_){
        int c=u&31; int i=(u>>5)&31; int o=u>>10;
        g_w1t[u] = up1_w[c*288 + i*9 + o]; return;
    }
    u -= 9*C_*C_;
    if (u < C_*C_){
        int c=u&31, j=u>>5;
        g_u2t[u] = up2_w[c*32+j]; return;
    }
    u -= C_*C_;
    if (u < C_*C_){
        int c=u&31, j=u>>5;
        g_taT[u] = tau_w[c*32+j];
    }
}

// ---------------- stem: relu(conv3x3 1->32) -> g_state (channels-last) --------
__global__ __launch_bounds__(256) void k_stem(
    const float* __restrict__ x, const float* __restrict__ sw,
    const float* __restrict__ sb)
{
    __shared__ float sx[3*66];
    __shared__ float s_w[9*32];
    __shared__ float s_b[32];
    int tid=threadIdx.x;
    int x0 = blockIdx.x*PX, y = blockIdx.y, b = blockIdx.z;
    for (int e=tid;e<198;e+=256){
        int r=e/66, col=e%66;
        int gy=y+r-1, gx=x0+col-1;
        sx[e] = (gy>=0 && gy<H_ && gx>=0 && gx<W_) ? x[(b*H_+gy)*W_+gx] : 0.f;
    }
    for (int e=tid;e<288;e+=256){ int o=e>>5, c=e&31; s_w[e]=sw[c*9+o]; }
    if (tid<32) s_b[tid]=sb[tid];
    __syncthreads();
    int px=tid&63, c0=(tid>>6)<<3;
    float acc[8];
    #pragma unroll
    for(int i=0;i<8;i++) acc[i]=s_b[c0+i];
    #pragma unroll
    for (int o=0;o<9;o++){
        float v = sx[(o/3)*66 + px + (o%3)];
        #pragma unroll
        for(int i=0;i<8;i++) acc[i] = fmaf(v, s_w[o*32+c0+i], acc[i]);
    }
    int pix = (b*H_+y)*W_ + x0 + px;
    float4* out = (float4*)&g_state[(size_t)pix*32 + c0];
    out[0]=make_float4(fmaxf(acc[0],0.f),fmaxf(acc[1],0.f),fmaxf(acc[2],0.f),fmaxf(acc[3],0.f));
    out[1]=make_float4(fmaxf(acc[4],0.f),fmaxf(acc[5],0.f),fmaxf(acc[6],0.f),fmaxf(acc[7],0.f));
}

// ---------------- step-0 heavy conv: g_h = relu(conv3x3(g_state, up1)) --------
__global__ __launch_bounds__(256,3) void k_conv1(const float* __restrict__ up1_b)
{
    extern __shared__ float sm[];
    float* st  = sm;             // 3*66*33 = 6534 (padded to 6560)
    float* s_w = sm + 6560;      // 9216, layout [o][i][c]
    int tid=threadIdx.x;
    int x0=blockIdx.x*PX, y=blockIdx.y, b=blockIdx.z;
    // fill halo tile: 3 rows x 66 cols x 32 ch, vectorized loads
    for (int e=tid;e<1584;e+=256){
        int c4=e&7; int col=(e>>3)%66; int r=e/528;
        int gy=y+r-1, gx=x0+col-1;
        float4 v=make_float4(0.f,0.f,0.f,0.f);
        if (gy>=0 && gy<H_ && gx>=0 && gx<W_)
            v = *(const float4*)&g_state[(size_t)((b*H_+gy)*W_+gx)*32 + c4*4];
        float* dp=&st[(r*66+col)*33 + c4*4];
        dp[0]=v.x; dp[1]=v.y; dp[2]=v.z; dp[3]=v.w;
    }
    // weights: coalesced copy of pre-transposed table
    for (int e=tid;e<2304;e+=256)
        ((float4*)s_w)[e]=((const float4*)g_w1t)[e];
    __syncthreads();
    int px = tid&63, c0=(tid>>6)<<3;
    u64 acc[4];
    acc[0]=f2_pack(up1_b[c0+0],up1_b[c0+1]);
    acc[1]=f2_pack(up1_b[c0+2],up1_b[c0+3]);
    acc[2]=f2_pack(up1_b[c0+4],up1_b[c0+5]);
    acc[3]=f2_pack(up1_b[c0+6],up1_b[c0+7]);
    #pragma unroll
    for (int o=0;o<9;o++){
        const float* stc = &st[((o/3)*66 + px + (o%3))*33];
        const float* wb  = &s_w[o*1024 + c0];
        #pragma unroll 8
        for (int i=0;i<32;i++){
            u64 v = f2_splat(stc[i]);
            ulonglong2 w01 = *(const ulonglong2*)(wb + i*32);
            ulonglong2 w23 = *(const ulonglong2*)(wb + i*32 + 4);
            acc[0]=f2_fma(w01.x,v,acc[0]); acc[1]=f2_fma(w01.y,v,acc[1]);
            acc[2]=f2_fma(w23.x,v,acc[2]); acc[3]=f2_fma(w23.y,v,acc[3]);
        }
    }
    int pix = (b*H_+y)*W_ + x0 + px;
    float r[8];
    f2_unpack(acc[0],r[0],r[1]); f2_unpack(acc[1],r[2],r[3]);
    f2_unpack(acc[2],r[4],r[5]); f2_unpack(acc[3],r[6],r[7]);
    float4* o4 = (float4*)&g_h[(size_t)pix*32 + c0];
    o4[0] = make_float4(fmaxf(r[0],0.f),fmaxf(r[1],0.f),fmaxf(r[2],0.f),fmaxf(r[3],0.f));
    o4[1] = make_float4(fmaxf(r[4],0.f),fmaxf(r[5],0.f),fmaxf(r[6],0.f),fmaxf(r[7],0.f));
}

// ---------------- shared VQ phase-2: 2-pass scores GEMM + warp argmin ---------
// codes per lane: pass0 -> lane*4..+3, pass1 -> 128+lane*4..+3 (conflict-free LDS)
__device__ __forceinline__ void vq_phase2(
    const float* __restrict__ s_t,   // [32][64] z' transposed, pad 64
    const float* __restrict__ cb_t,  // [32 ch][256 codes]
    const float* __restrict__ s_cn,  // [256] 0.5||c||^2
    int pix0, unsigned char* __restrict__ dst)
{
    int lane=threadIdx.x&31, w=threadIdx.x>>5;
    int p0=w*8;
    u64 best[8];
    #pragma unroll
    for (int j=0;j<8;j++) best[j]=~0ull;
    #pragma unroll
    for (int pass=0; pass<2; pass++){
        int cbase = pass*128 + lane*4;
        u64 acc[4][4];
        #pragma unroll
        for(int i=0;i<4;i++){acc[i][0]=0;acc[i][1]=0;acc[i][2]=0;acc[i][3]=0;}
        #pragma unroll 8
        for (int k=0;k<32;k++){
            ulonglong2 z01=*(const ulonglong2*)&s_t[k*64+p0];
            ulonglong2 z23=*(const ulonglong2*)&s_t[k*64+p0+4];
            float4 cv=*(const float4*)&cb_t[k*256+cbase];
            u64 cc0=f2_splat(cv.x), cc1=f2_splat(cv.y),
                cc2=f2_splat(cv.z), cc3=f2_splat(cv.w);
            acc[0][0]=f2_fma(z01.x,cc0,acc[0][0]); acc[0][1]=f2_fma(z01.y,cc0,acc[0][1]);
            acc[0][2]=f2_fma(z23.x,cc0,acc[0][2]); acc[0][3]=f2_fma(z23.y,cc0,acc[0][3]);
            acc[1][0]=f2_fma(z01.x,cc1,acc[1][0]); acc[1][1]=f2_fma(z01.y,cc1,acc[1][1]);
            acc[1][2]=f2_fma(z23.x,cc1,acc[1][2]); acc[1][3]=f2_fma(z23.y,cc1,acc[1][3]);
            acc[2][0]=f2_fma(z01.x,cc2,acc[2][0]); acc[2][1]=f2_fma(z01.y,cc2,acc[2][1]);
            acc[2][2]=f2_fma(z23.x,cc2,acc[2][2]); acc[2][3]=f2_fma(z23.y,cc2,acc[2][3]);
            acc[3][0]=f2_fma(z01.x,cc3,acc[3][0]); acc[3][1]=f2_fma(z01.y,cc3,acc[3][1]);
            acc[3][2]=f2_fma(z23.x,cc3,acc[3][2]); acc[3][3]=f2_fma(z23.y,cc3,acc[3][3]);
        }
        #pragma unroll
        for(int i=0;i<4;i++){
            float cn=s_cn[cbase+i];
            #pragma unroll
            for(int j=0;j<4;j++){
                float lo,hi; f2_unpack(acc[i][j],lo,hi);
                u64 keyl=(((u64)ford(cn-lo))<<8)|(u32)(cbase+i);
                u64 keyh=(((u64)ford(cn-hi))<<8)|(u32)(cbase+i);
                if (keyl<best[2*j])   best[2*j]=keyl;
                if (keyh<best[2*j+1]) best[2*j+1]=keyh;
            }
        }
    }
    u64 packed=0;
    #pragma unroll
    for(int pp=0;pp<8;pp++){
        u64 kk=best[pp];
        #pragma unroll
        for(int off=16;off>0;off>>=1){
            u64 o=__shfl_xor_sync(0xffffffffu,kk,off);
            kk = (o<kk)?o:kk;
        }
        packed |= (kk&0xffull) << (8*pp);
    }
    if (lane==0) *(u64*)&dst[pix0+p0] = packed;
}

// ---------------- step 0 mix + VQ (continuous state) --------------------------
__global__ __launch_bounds__(256,3) void k_mixvq0(
    const float* __restrict__ up2_b, const float* __restrict__ tau_b)
{
    extern __shared__ float sm[];
    float* cb_t = sm;            // 8192
    float* sh   = cb_t+8192;     // 64*33
    float* sst  = sh+2112;       // 64*33
    float* s_t  = sst+2112;      // 32*64
    float* s_u2 = s_t+2048;      // 1024 [j][c]
    float* s_ta = s_u2+1024;     // 1024 [j][c]
    float* s_cn = s_ta+1024;     // 256
    int tid=threadIdx.x;
    int x0=blockIdx.x*PX, y=blockIdx.y, b=blockIdx.z;
    int pix0 = (b*H_+y)*W_ + x0;
    for (int e=tid;e<2048;e+=256) ((float4*)cb_t)[e]=((const float4*)g_cbT)[e];
    {
        const float4* gh=(const float4*)&g_h[(size_t)pix0*32];
        const float4* gs=(const float4*)&g_state[(size_t)pix0*32];
        for (int e=tid;e<512;e+=256){
            float4 a=gh[e], c=gs[e];
            int px=e>>3, ch=(e&7)*4;
            float* dh=&sh [px*33+ch]; dh[0]=a.x;dh[1]=a.y;dh[2]=a.z;dh[3]=a.w;
            float* ds=&sst[px*33+ch]; ds[0]=c.x;ds[1]=c.y;ds[2]=c.z;ds[3]=c.w;
        }
    }
    for (int e=tid;e<256;e+=256) ((float4*)s_u2)[e]=((const float4*)g_u2t)[e];
    for (int e=tid;e<256;e+=256) ((float4*)s_ta)[e]=((const float4*)g_taT)[e];
    s_cn[tid]=g_cnh[tid];
    __syncthreads();
    {
        int px=tid&63, c0=(tid>>6)<<3;
        u64 d[4]={f2_pack(up2_b[c0],up2_b[c0+1]),f2_pack(up2_b[c0+2],up2_b[c0+3]),
                  f2_pack(up2_b[c0+4],up2_b[c0+5]),f2_pack(up2_b[c0+6],up2_b[c0+7])};
        u64 t[4]={f2_pack(tau_b[c0],tau_b[c0+1]),f2_pack(tau_b[c0+2],tau_b[c0+3]),
                  f2_pack(tau_b[c0+4],tau_b[c0+5]),f2_pack(tau_b[c0+6],tau_b[c0+7])};
        #pragma unroll 8
        for (int j=0;j<32;j++){
            u64 hv=f2_splat(sh [px*33+j]);
            u64 sv=f2_splat(sst[px*33+j]);
            ulonglong2 w01=*(const ulonglong2*)&s_u2[j*32+c0];
            ulonglong2 w23=*(const ulonglong2*)&s_u2[j*32+c0+4];
            ulonglong2 q01=*(const ulonglong2*)&s_ta[j*32+c0];
            ulonglong2 q23=*(const ulonglong2*)&s_ta[j*32+c0+4];
            d[0]=f2_fma(w01.x,hv,d[0]); d[1]=f2_fma(w01.y,hv,d[1]);
            d[2]=f2_fma(w23.x,hv,d[2]); d[3]=f2_fma(w23.y,hv,d[3]);
            t[0]=f2_fma(q01.x,sv,t[0]); t[1]=f2_fma(q01.y,sv,t[1]);
            t[2]=f2_fma(q23.x,sv,t[2]); t[3]=f2_fma(q23.y,sv,t[3]);
        }
        #pragma unroll
        for (int jj=0;jj<4;jj++){
            float dl,dh,tl,th; f2_unpack(d[jj],dl,dh); f2_unpack(t[jj],tl,th);
            float sl=sst[px*33+c0+2*jj], shh=sst[px*33+c0+2*jj+1];
            float bl=sigm(tl), bh=sigm(th);
            s_t[(c0+2*jj  )*64+px]=dl+bl*(sl -dl);
            s_t[(c0+2*jj+1)*64+px]=dh+bh*(shh-dh);
        }
    }
    __syncthreads();
    vq_phase2(s_t, cb_t, s_cn, pix0, g_idx[0]);
}

// ---------------- steps 1..4 : fully table-driven, idx -> idx -----------------
__global__ __launch_bounds__(256,3) void k_step(
    const float* __restrict__ up2_b, const float* __restrict__ up1_b, int src)
{
    extern __shared__ float sm[];
    float* cb_t = sm;            // 8192  [ch][code]
    float* sh   = cb_t+8192;     // 64*33
    float* s_t  = sh+2112;       // 32*64
    float* s_u2 = s_t+2048;      // 1024 [j][c]
    float* s_cn = s_u2+1024;     // 256
    int*   s_id = (int*)(s_cn+256); // 3*66
    const unsigned char* __restrict__ gin = g_idx[src];
    unsigned char* __restrict__ gout = g_idx[src^1];
    int tid=threadIdx.x;
    int x0=blockIdx.x*PX, y=blockIdx.y, b=blockIdx.z;
    int pix0 = (b*H_+y)*W_ + x0;
    for (int e=tid;e<2048;e+=256) ((float4*)cb_t)[e]=((const float4*)g_cbT)[e];
    for (int e=tid;e<256;e+=256) ((float4*)s_u2)[e]=((const float4*)g_u2t)[e];
    s_cn[tid]=g_cnh[tid];
    for (int e=tid;e<198;e+=256){
        int r=e/66, col=e%66;
        int gy=y+r-1, gx=x0+col-1;
        s_id[e] = (gy>=0 && gy<H_ && gx>=0 && gx<W_) ? (int)gin[(b*H_+gy)*W_+gx] : -1;
    }
    __syncthreads();
    // phase 1a: h = relu(up1_b + sum of 9 table rows)  (coalesced-table mapping)
    {
        int pxa=tid>>2, ca=(tid&3)<<3;
        float4 b0=*(const float4*)&up1_b[ca];
        float4 b1=*(const float4*)&up1_b[ca+4];
        u64 a[4]={f2_pack(b0.x,b0.y),f2_pack(b0.z,b0.w),
                  f2_pack(b1.x,b1.y),f2_pack(b1.z,b1.w)};
        #pragma unroll
        for(int o=0;o<9;o++){
            int kk=s_id[(o/3)*66+pxa+(o%3)];
            if (kk>=0){
                const ulonglong2* tp=(const ulonglong2*)&g_up1_tab[(size_t)((o<<8)+kk)*32+ca];
                ulonglong2 v0=tp[0], v1=tp[1];
                a[0]=f2_add(a[0],v0.x); a[1]=f2_add(a[1],v0.y);
                a[2]=f2_add(a[2],v1.x); a[3]=f2_add(a[3],v1.y);
            }
        }
        #pragma unroll
        for(int j=0;j<4;j++){
            float lo,hi; f2_unpack(a[j],lo,hi);
            sh[pxa*33+ca+2*j  ]=fmaxf(lo,0.f);
            sh[pxa*33+ca+2*j+1]=fmaxf(hi,0.f);
        }
    }
    __syncthreads();
    // phase 1b: delta = up2@h + b ; beta = sigmoid(tau_tab[k]) ; z' = mix
    {
        int px=tid&63, c0=(tid>>6)<<3;
        int kself = s_id[66 + px + 1];
        u64 d[4]={f2_pack(up2_b[c0],up2_b[c0+1]),f2_pack(up2_b[c0+2],up2_b[c0+3]),
                  f2_pack(up2_b[c0+4],up2_b[c0+5]),f2_pack(up2_b[c0+6],up2_b[c0+7])};
        #pragma unroll 8
        for (int j=0;j<32;j++){
            u64 hv=f2_splat(sh[px*33+j]);
            ulonglong2 w01=*(const ulonglong2*)&s_u2[j*32+c0];
            ulonglong2 w23=*(const ulonglong2*)&s_u2[j*32+c0+4];
            d[0]=f2_fma(w01.x,hv,d[0]); d[1]=f2_fma(w01.y,hv,d[1]);
            d[2]=f2_fma(w23.x,hv,d[2]); d[3]=f2_fma(w23.y,hv,d[3]);
        }
        float4 t0=*(const float4*)&g_tau_tab[kself*32+c0];
        float4 t1=*(const float4*)&g_tau_tab[kself*32+c0+4];
        float tp[8]={t0.x,t0.y,t0.z,t0.w,t1.x,t1.y,t1.z,t1.w};
        #pragma unroll
        for (int jj=0;jj<4;jj++){
            float dl,dh; f2_unpack(d[jj],dl,dh);
            float sl =cb_t[(c0+2*jj  )*256+kself];
            float shh=cb_t[(c0+2*jj+1)*256+kself];
            float bl=sigm(tp[2*jj]), bh=sigm(tp[2*jj+1]);
            s_t[(c0+2*jj  )*64+px]=dl+bl*(sl -dl);
            s_t[(c0+2*jj+1)*64+px]=dh+bh*(shh-dh);
        }
    }
    __syncthreads();
    vq_phase2(s_t, cb_t, s_cn, pix0, gout);
}

// ---------------- decode: pure LUT ---------------------------------------------
__global__ __launch_bounds__(256) void k_dec(float* __restrict__ out, int fin)
{
    __shared__ float tab[256];
    tab[threadIdx.x]=g_dec_tab[threadIdx.x];
    __syncthreads();
    int t=blockIdx.x*256+threadIdx.x;
    uchar4 iv=*(const uchar4*)&g_idx[fin][t*4];
    ((float4*)out)[t]=make_float4(tab[iv.x],tab[iv.y],tab[iv.z],tab[iv.w]);
}

// ---------------- launch --------------------------------------------------------
extern "C" void kernel_launch(void* const* d_in, const int* in_sizes, int n_in,
                              void* d_out, int out_size)
{
    const float* x      =(const float*)d_in[0];
    const float* stem_w =(const float*)d_in[1];
    const float* stem_b =(const float*)d_in[2];
    const float* up1_w  =(const float*)d_in[3];
    const float* up1_b  =(const float*)d_in[4];
    const float* up2_w  =(const float*)d_in[5];
    const float* up2_b  =(const float*)d_in[6];
    const float* tau_w  =(const float*)d_in[7];
    const float* tau_b  =(const float*)d_in[8];
    const float* cb     =(const float*)d_in[9];
    const float* dec_w  =(const float*)d_in[10];
    const float* dec_b  =(const float*)d_in[11];
    (void)in_sizes; (void)n_in; (void)out_size;

    const size_t sm_conv1=(size_t)(6560+9216)*4;
    const size_t sm_mix  =(size_t)(8192+2112+2112+2048+1024+1024+256)*4;
    const size_t sm_step =(size_t)(8192+2112+2048+1024+256)*4 + 198*4;
    cudaFuncSetAttribute(k_conv1,  cudaFuncAttributeMaxDynamicSharedMemorySize,(int)sm_conv1);
    cudaFuncSetAttribute(k_mixvq0, cudaFuncAttributeMaxDynamicSharedMemorySize,(int)sm_mix);
    cudaFuncSetAttribute(k_step,   cudaFuncAttributeMaxDynamicSharedMemorySize,(int)sm_step);

    dim3 grid(W_/PX, H_, B_);
    k_pre   <<<398, 256>>>(up1_w, tau_w, tau_b, cb, dec_w, dec_b, up2_w);
    k_stem  <<<grid,256>>>(x, stem_w, stem_b);
    k_conv1 <<<grid,256,sm_conv1>>>(up1_b);
    k_mixvq0<<<grid,256,sm_mix  >>>(up2_b, tau_b);
    for (int t=1;t<5;t++)
        k_step<<<grid,256,sm_step>>>(up2_b, up1_b, (t-1)&1);
    k_dec   <<<1024,256>>>((float*)d_out, 0);
}